// round 15
// baseline (speedup 1.0000x reference)
#include <cuda_runtime.h>
#include <math.h>
#include <stdint.h>

// Problem constants
#define BSZ   2
#define SEQ   2048
#define EMB   2048
#define NH    32
#define HD    64
#define KVHN  8
#define KVD   512
#define GRP   4
#define MTOT  (BSZ*SEQ)   // 4096

// Scratch — device globals, referenced ONLY inside device code.
__device__ __align__(16) float g_q[MTOT * EMB];
__device__ __align__(16) float g_k[MTOT * KVD];
__device__ __align__(16) float g_v[MTOT * KVD];
__device__ __align__(16) float g_attn[MTOT * EMB];

// ---------------------------------------------------------------------------
// PTX helpers
// ---------------------------------------------------------------------------
__device__ __forceinline__ uint32_t smem_u32(const void* p) {
    return (uint32_t)__cvta_generic_to_shared(p);
}
__device__ __forceinline__ uint32_t pack_bf16x2(float v0, float v1) {
    uint32_t r;
    asm("cvt.rn.bf16x2.f32 %0, %1, %2;" : "=r"(r) : "f"(v1), "f"(v0));
    return r;
}
__device__ __forceinline__ void split_pair(float v0, float v1, uint32_t& hi, uint32_t& lo) {
    hi = pack_bf16x2(v0, v1);
    float h0 = __uint_as_float(hi << 16);
    float h1 = __uint_as_float(hi & 0xffff0000u);
    lo = pack_bf16x2(v0 - h0, v1 - h1);
}
__device__ __forceinline__ void mma_bf16(float* c, const uint32_t* a, const uint32_t* b) {
    asm volatile(
        "mma.sync.aligned.m16n8k16.row.col.f32.bf16.bf16.f32 "
        "{%0,%1,%2,%3},{%4,%5,%6,%7},{%8,%9},{%0,%1,%2,%3};"
        : "+f"(c[0]), "+f"(c[1]), "+f"(c[2]), "+f"(c[3])
        : "r"(a[0]), "r"(a[1]), "r"(a[2]), "r"(a[3]), "r"(b[0]), "r"(b[1]));
}
__device__ __forceinline__ void ldsm4(uint32_t* r, uint32_t addr) {
    asm volatile("ldmatrix.sync.aligned.m8n8.x4.shared.b16 {%0,%1,%2,%3}, [%4];"
        : "=r"(r[0]), "=r"(r[1]), "=r"(r[2]), "=r"(r[3]) : "r"(addr));
}
__device__ __forceinline__ void ldsm4t(uint32_t* r, uint32_t addr) {
    asm volatile("ldmatrix.sync.aligned.m8n8.x4.trans.shared.b16 {%0,%1,%2,%3}, [%4];"
        : "=r"(r[0]), "=r"(r[1]), "=r"(r[2]), "=r"(r[3]) : "r"(addr));
}

// ---------------------------------------------------------------------------
// Split-bf16 tensor-core GEMM (R12 shape + fused hi/lo B ldsm4t):
// C[M,N] = A[M,K] @ B[K,N]; CTA tile 128x128, BK=32, 256 threads (8 warps 2x4).
// ---------------------------------------------------------------------------
#define BM 128
#define BN 128
#define BK 32
#define A_ST   5120     // stage stride, uint16 elems (128*40)
#define B_ST   4352     // stage stride, uint16 elems (32*136)
#define OFF_AL (2*A_ST)
#define OFF_BH (4*A_ST)
#define OFF_BL (4*A_ST + 2*B_ST)
#define SMEM_GEMM ((4*A_ST + 4*B_ST) * 2)   // 75776 B
#define GTHREADS 256

__device__ __forceinline__
void gemm_body(const float* __restrict__ A, const float* __restrict__ Bg,
               float* __restrict__ C, int N, int K, int bx)
{
    extern __shared__ char smraw[];
    uint16_t* Ah = (uint16_t*)smraw;
    uint16_t* Al = Ah + OFF_AL;
    uint16_t* Bh = Ah + OFF_BH;
    uint16_t* Bl = Ah + OFF_BL;

    const int tid  = threadIdx.x;
    const int lane = tid & 31;
    const int wid  = tid >> 5;
    const int wm   = wid & 1;        // 0..1 -> 64-row slice
    const int wn   = wid >> 1;       // 0..3 -> 32-col slice
    const int m0   = blockIdx.y * BM;
    const int n0   = bx * BN;
    const int lg   = lane >> 2;
    const int lt   = lane & 3;

    // LDSM lane-address components (byte offsets)
    const int rowA = ((lane >> 3) & 1) * 8 + (lane & 7);
    const int colA = (lane >> 4) * 8;
    const uint32_t aLane = (uint32_t)(rowA * 40 + colA) * 2;

    const uint32_t ahB0 = smem_u32(Ah);
    const uint32_t alB0 = smem_u32(Al);
    // fused B: lanes 0-15 read Bh (matrices 0,1), lanes 16-31 read Bl (2,3)
    const uint32_t bSel0 = ((lane < 16) ? smem_u32(Bh) : smem_u32(Bl))
                         + (uint32_t)((lane & 15) * 136) * 2;

    // per-thread fill coordinates (4 float4 each for A and B)
    int aR[4], aK[4], bR[4], bC[4];
    #pragma unroll
    for (int i = 0; i < 4; i++) {
        int idx4 = tid + i * GTHREADS;  // 0..1023
        aR[i] = idx4 >> 3;              // 0..127
        aK[i] = (idx4 & 7) * 4;         // 0..28
        bR[i] = idx4 >> 5;              // 0..31
        bC[i] = (idx4 & 31) * 4;        // 0..124
    }

    float4 pa[4], pb[4];
    #pragma unroll
    for (int i = 0; i < 4; i++) {
        pa[i] = *(const float4*)(A  + (size_t)(m0 + aR[i]) * K + aK[i]);
        pb[i] = *(const float4*)(Bg + (size_t)bR[i] * N + n0 + bC[i]);
    }

    float acc[4][4][4] = {};
    const int nk = K / BK;

    for (int c = 0; c < nk; c++) {
        const int cur = c & 1;
        // ---- convert + store current chunk ----
        #pragma unroll
        for (int i = 0; i < 4; i++) {
            uint32_t h01, l01, h23, l23;
            split_pair(pa[i].x, pa[i].y, h01, l01);
            split_pair(pa[i].z, pa[i].w, h23, l23);
            int offA = cur * A_ST + aR[i] * 40 + aK[i];
            *(uint2*)(Ah + offA) = make_uint2(h01, h23);
            *(uint2*)(Al + offA) = make_uint2(l01, l23);

            split_pair(pb[i].x, pb[i].y, h01, l01);
            split_pair(pb[i].z, pb[i].w, h23, l23);
            int offB = cur * B_ST + bR[i] * 136 + bC[i];
            *(uint2*)(Bh + offB) = make_uint2(h01, h23);
            *(uint2*)(Bl + offB) = make_uint2(l01, l23);
        }
        // ---- prefetch next chunk (LDG latency overlaps mma below) ----
        if (c + 1 < nk) {
            #pragma unroll
            for (int i = 0; i < 4; i++) {
                pa[i] = *(const float4*)(A  + (size_t)(m0 + aR[i]) * K + (c + 1) * BK + aK[i]);
                pb[i] = *(const float4*)(Bg + (size_t)((c + 1) * BK + bR[i]) * N + n0 + bC[i]);
            }
        }
        __syncthreads();

        // ---- mma from bf16 smem via LDSM ----
        const uint32_t ahB = ahB0 + cur * (A_ST * 2) + (wm * 64 * 40) * 2 + aLane;
        const uint32_t alB = alB0 + cur * (A_ST * 2) + (wm * 64 * 40) * 2 + aLane;
        const uint32_t bB  = bSel0 + cur * (B_ST * 2) + (wn * 32) * 2;

        #pragma unroll
        for (int ks = 0; ks < 2; ks++) {
            const int k = ks * 16;
            uint32_t ah[4][4], al[4][4];
            #pragma unroll
            for (int mi = 0; mi < 4; mi++) {
                uint32_t off = (uint32_t)(mi * 16 * 40 + k) * 2;
                ldsm4(ah[mi], ahB + off);
                ldsm4(al[mi], alB + off);
            }
            #pragma unroll
            for (int ni = 0; ni < 4; ni++) {
                uint32_t bb[4];  // {bh0,bh1,bl0,bl1}
                ldsm4t(bb, bB + (uint32_t)(k * 136 + ni * 8) * 2);
                #pragma unroll
                for (int mi = 0; mi < 4; mi++) {
                    mma_bf16(acc[mi][ni], ah[mi], bb);
                    mma_bf16(acc[mi][ni], ah[mi], bb + 2);
                    mma_bf16(acc[mi][ni], al[mi], bb);
                }
            }
        }
        if (c + 1 < nk) __syncthreads();
    }

    // ---- store C ----
    #pragma unroll
    for (int mi = 0; mi < 4; mi++) {
        #pragma unroll
        for (int ni = 0; ni < 4; ni++) {
            int row = m0 + wm * 64 + mi * 16 + lg;
            int col = n0 + wn * 32 + ni * 8 + 2 * lt;
            float2 v0 = make_float2(acc[mi][ni][0], acc[mi][ni][1]);
            float2 v1 = make_float2(acc[mi][ni][2], acc[mi][ni][3]);
            *(float2*)(C + (size_t)row * N + col)       = v0;
            *(float2*)(C + (size_t)(row + 8) * N + col) = v1;
        }
    }
}

// Fused Q/K/V projection: grid.x 0..15 -> Q, 16..19 -> K, 20..23 -> V
__global__ __launch_bounds__(GTHREADS)
void k_proj_qkv(const float* __restrict__ x, const float* __restrict__ Wq,
                const float* __restrict__ Wk, const float* __restrict__ Wv) {
    int bx = blockIdx.x;
    if (bx < 16)      gemm_body(x, Wq, g_q, EMB, EMB, bx);
    else if (bx < 20) gemm_body(x, Wk, g_k, KVD, EMB, bx - 16);
    else              gemm_body(x, Wv, g_v, KVD, EMB, bx - 20);
}
__global__ __launch_bounds__(GTHREADS)
void k_out_proj(const float* __restrict__ Wo, float* __restrict__ out) {
    gemm_body(g_attn, Wo, out, EMB, EMB, blockIdx.x);
}

// ---------------------------------------------------------------------------
// Tensor-core causal GQA flash attention v3: 4 heads per CTA share one K/V
// smem fill+split; fused hi/lo ldsm4 fragment loads. 512 threads, 16 warps:
// warp w -> head (w>>2) of the kv-group, q-rows (w&3)*16.
// Grid (SEQ/64, KVHN, BSZ).
// ---------------------------------------------------------------------------
#define PK 72   // bf16 row pitch (144 B)
#define ATHREADS 512

__global__ __launch_bounds__(ATHREADS)
void attn_tc()
{
    __shared__ uint16_t sKh[64][PK], sKl[64][PK];
    __shared__ uint16_t sVh[64][PK], sVl[64][PK];

    const int qt = blockIdx.x, kvh = blockIdx.y, b = blockIdx.z;
    const int tid = threadIdx.x;
    const int w = tid >> 5, lane = tid & 31;
    const int h = kvh * GRP + (w >> 2);    // query head for this warp
    const int wq = w & 3;                  // q-row slice within tile
    const int lg = lane >> 2, lt = lane & 3;
    const int q0 = qt * 64;
    const int qrow = q0 + wq * 16;
    const float qscale = 0.125f * 1.44269504f;

    // fused hi/lo LDSM lane addresses (lanes 0-15 -> hi array, 16-31 -> lo)
    const uint32_t kB = ((lane < 16) ? smem_u32(sKh) : smem_u32(sKl))
                      + (uint32_t)((lane & 7) * PK + ((lane >> 3) & 1) * 8) * 2;
    const uint32_t vB = ((lane < 16) ? smem_u32(sVh) : smem_u32(sVl))
                      + (uint32_t)((lane & 15) * PK) * 2;

    // Q fragments (hi/lo), loaded once
    uint32_t qh[4][4], ql[4][4];
    {
        const float* qp = g_q + (size_t)(b * SEQ + qrow) * EMB + h * HD;
        #pragma unroll
        for (int ks = 0; ks < 4; ks++) {
            int d0 = ks * 16 + 2 * lt;
            float2 v00 = *(const float2*)(qp + (size_t)lg * EMB + d0);
            float2 v10 = *(const float2*)(qp + (size_t)(lg + 8) * EMB + d0);
            float2 v01 = *(const float2*)(qp + (size_t)lg * EMB + d0 + 8);
            float2 v11 = *(const float2*)(qp + (size_t)(lg + 8) * EMB + d0 + 8);
            split_pair(v00.x * qscale, v00.y * qscale, qh[ks][0], ql[ks][0]);
            split_pair(v10.x * qscale, v10.y * qscale, qh[ks][1], ql[ks][1]);
            split_pair(v01.x * qscale, v01.y * qscale, qh[ks][2], ql[ks][2]);
            split_pair(v11.x * qscale, v11.y * qscale, qh[ks][3], ql[ks][3]);
        }
    }

    float m_lo = -1e30f, m_hi = -1e30f;
    float l_lo = 0.f, l_hi = 0.f;
    float o[8][4] = {};

    for (int kt = 0; kt <= qt; kt++) {
        const int k0 = kt * 64;
        __syncthreads();
        // fill K/V tiles as bf16 hi/lo (split once, shared by 4 heads)
        #pragma unroll
        for (int i = 0; i < 2; i++) {
            int idx = tid + i * ATHREADS;
            int r = idx >> 4, c4 = (idx & 15) * 4;
            size_t base = (size_t)(b * SEQ + k0 + r) * KVD + kvh * HD + c4;
            float4 kv = *(const float4*)(g_k + base);
            float4 vv = *(const float4*)(g_v + base);
            uint32_t h01, l01, h23, l23;
            split_pair(kv.x, kv.y, h01, l01);
            split_pair(kv.z, kv.w, h23, l23);
            *(uint2*)&sKh[r][c4] = make_uint2(h01, h23);
            *(uint2*)&sKl[r][c4] = make_uint2(l01, l23);
            split_pair(vv.x, vv.y, h01, l01);
            split_pair(vv.z, vv.w, h23, l23);
            *(uint2*)&sVh[r][c4] = make_uint2(h01, h23);
            *(uint2*)&sVl[r][c4] = make_uint2(l01, l23);
        }
        __syncthreads();

        // ---- S = Q @ K^T (fused hi/lo ldsm4) ----
        float s[8][4] = {};
        #pragma unroll
        for (int ks = 0; ks < 4; ks++) {
            #pragma unroll
            for (int nb = 0; nb < 8; nb++) {
                uint32_t kk[4];   // {kh0,kh1,kl0,kl1}
                ldsm4(kk, kB + (uint32_t)(nb * 8 * PK + ks * 16) * 2);
                mma_bf16(s[nb], qh[ks], kk);
                mma_bf16(s[nb], qh[ks], kk + 2);
                mma_bf16(s[nb], ql[ks], kk);
            }
        }

        // ---- causal mask (diagonal tile) ----
        if (kt == qt) {
            #pragma unroll
            for (int nb = 0; nb < 8; nb++) {
                int col = k0 + nb * 8 + 2 * lt;
                int rlo = qrow + lg, rhi = qrow + lg + 8;
                if (col     > rlo) s[nb][0] = -1e30f;
                if (col + 1 > rlo) s[nb][1] = -1e30f;
                if (col     > rhi) s[nb][2] = -1e30f;
                if (col + 1 > rhi) s[nb][3] = -1e30f;
            }
        }

        // ---- online softmax in registers ----
        float tm_lo = -1e30f, tm_hi = -1e30f;
        #pragma unroll
        for (int nb = 0; nb < 8; nb++) {
            tm_lo = fmaxf(tm_lo, fmaxf(s[nb][0], s[nb][1]));
            tm_hi = fmaxf(tm_hi, fmaxf(s[nb][2], s[nb][3]));
        }
        #pragma unroll
        for (int off = 1; off <= 2; off <<= 1) {
            tm_lo = fmaxf(tm_lo, __shfl_xor_sync(0xffffffffu, tm_lo, off));
            tm_hi = fmaxf(tm_hi, __shfl_xor_sync(0xffffffffu, tm_hi, off));
        }
        float mn_lo = fmaxf(m_lo, tm_lo);
        float mn_hi = fmaxf(m_hi, tm_hi);
        float sc_lo = exp2f(m_lo - mn_lo);
        float sc_hi = exp2f(m_hi - mn_hi);
        m_lo = mn_lo; m_hi = mn_hi;

        float ps_lo = 0.f, ps_hi = 0.f;
        #pragma unroll
        for (int nb = 0; nb < 8; nb++) {
            s[nb][0] = exp2f(s[nb][0] - mn_lo);
            s[nb][1] = exp2f(s[nb][1] - mn_lo);
            s[nb][2] = exp2f(s[nb][2] - mn_hi);
            s[nb][3] = exp2f(s[nb][3] - mn_hi);
            ps_lo += s[nb][0] + s[nb][1];
            ps_hi += s[nb][2] + s[nb][3];
        }
        l_lo = l_lo * sc_lo + ps_lo;
        l_hi = l_hi * sc_hi + ps_hi;
        #pragma unroll
        for (int nbd = 0; nbd < 8; nbd++) {
            o[nbd][0] *= sc_lo; o[nbd][1] *= sc_lo;
            o[nbd][2] *= sc_hi; o[nbd][3] *= sc_hi;
        }

        // ---- O += P @ V (fused hi/lo ldsm4t) ----
        #pragma unroll
        for (int kb = 0; kb < 4; kb++) {
            uint32_t ph[4], pl[4];
            split_pair(s[2*kb][0],     s[2*kb][1],     ph[0], pl[0]);
            split_pair(s[2*kb][2],     s[2*kb][3],     ph[1], pl[1]);
            split_pair(s[2*kb + 1][0], s[2*kb + 1][1], ph[2], pl[2]);
            split_pair(s[2*kb + 1][2], s[2*kb + 1][3], ph[3], pl[3]);
            #pragma unroll
            for (int nbd = 0; nbd < 8; nbd++) {
                uint32_t vv[4];   // {vh0,vh1,vl0,vl1}
                ldsm4t(vv, vB + (uint32_t)(kb * 16 * PK + nbd * 8) * 2);
                mma_bf16(o[nbd], ph, vv);
                mma_bf16(o[nbd], ph, vv + 2);
                mma_bf16(o[nbd], pl, vv);
            }
        }
    }

    // ---- finalize ----
    #pragma unroll
    for (int off = 1; off <= 2; off <<= 1) {
        l_lo += __shfl_xor_sync(0xffffffffu, l_lo, off);
        l_hi += __shfl_xor_sync(0xffffffffu, l_hi, off);
    }
    float inv_lo = 1.0f / l_lo, inv_hi = 1.0f / l_hi;
    float* op = g_attn + (size_t)(b * SEQ + qrow) * EMB + h * HD;
    #pragma unroll
    for (int nbd = 0; nbd < 8; nbd++) {
        int dcol = nbd * 8 + 2 * lt;
        *(float2*)(op + (size_t)lg * EMB + dcol) =
            make_float2(o[nbd][0] * inv_lo, o[nbd][1] * inv_lo);
        *(float2*)(op + (size_t)(lg + 8) * EMB + dcol) =
            make_float2(o[nbd][2] * inv_hi, o[nbd][3] * inv_hi);
    }
}

// ---------------------------------------------------------------------------
extern "C" void kernel_launch(void* const* d_in, const int* in_sizes, int n_in,
                              void* d_out, int out_size)
{
    const float* x  = (const float*)d_in[0];
    const float* Wq = (const float*)d_in[1];
    const float* Wk = (const float*)d_in[2];
    const float* Wv = (const float*)d_in[3];
    const float* Wo = (const float*)d_in[4];
    float* out = (float*)d_out;

    cudaFuncSetAttribute(k_proj_qkv, cudaFuncAttributeMaxDynamicSharedMemorySize, SMEM_GEMM);
    cudaFuncSetAttribute(k_out_proj, cudaFuncAttributeMaxDynamicSharedMemorySize, SMEM_GEMM);

    k_proj_qkv<<<dim3(24, MTOT / BM), GTHREADS, SMEM_GEMM>>>(x, Wq, Wk, Wv);
    attn_tc<<<dim3(SEQ / 64, KVHN, BSZ), ATHREADS>>>();
    k_out_proj<<<dim3(EMB / BN, MTOT / BM), GTHREADS, SMEM_GEMM>>>(Wo, out);
}

// round 16
// speedup vs baseline: 1.0796x; 1.0796x over previous
#include <cuda_runtime.h>
#include <math.h>
#include <stdint.h>

// Problem constants
#define BSZ   2
#define SEQ   2048
#define EMB   2048
#define NH    32
#define HD    64
#define KVHN  8
#define KVD   512
#define GRP   4
#define MTOT  (BSZ*SEQ)   // 4096

// Scratch — device globals, referenced ONLY inside device code.
__device__ __align__(16) float g_q[MTOT * EMB];
__device__ __align__(16) float g_k[MTOT * KVD];
__device__ __align__(16) float g_v[MTOT * KVD];
__device__ __align__(16) float g_attn[MTOT * EMB];

// ---------------------------------------------------------------------------
// PTX helpers
// ---------------------------------------------------------------------------
__device__ __forceinline__ uint32_t smem_u32(const void* p) {
    return (uint32_t)__cvta_generic_to_shared(p);
}
__device__ __forceinline__ uint32_t pack_bf16x2(float v0, float v1) {
    uint32_t r;
    asm("cvt.rn.bf16x2.f32 %0, %1, %2;" : "=r"(r) : "f"(v1), "f"(v0));
    return r;
}
__device__ __forceinline__ void split_pair(float v0, float v1, uint32_t& hi, uint32_t& lo) {
    hi = pack_bf16x2(v0, v1);
    float h0 = __uint_as_float(hi << 16);
    float h1 = __uint_as_float(hi & 0xffff0000u);
    lo = pack_bf16x2(v0 - h0, v1 - h1);
}
__device__ __forceinline__ void mma_bf16(float* c, const uint32_t* a, const uint32_t* b) {
    asm volatile(
        "mma.sync.aligned.m16n8k16.row.col.f32.bf16.bf16.f32 "
        "{%0,%1,%2,%3},{%4,%5,%6,%7},{%8,%9},{%0,%1,%2,%3};"
        : "+f"(c[0]), "+f"(c[1]), "+f"(c[2]), "+f"(c[3])
        : "r"(a[0]), "r"(a[1]), "r"(a[2]), "r"(a[3]), "r"(b[0]), "r"(b[1]));
}
__device__ __forceinline__ void ldsm4(uint32_t* r, uint32_t addr) {
    asm volatile("ldmatrix.sync.aligned.m8n8.x4.shared.b16 {%0,%1,%2,%3}, [%4];"
        : "=r"(r[0]), "=r"(r[1]), "=r"(r[2]), "=r"(r[3]) : "r"(addr));
}
__device__ __forceinline__ void ldsm2(uint32_t* r, uint32_t addr) {
    asm volatile("ldmatrix.sync.aligned.m8n8.x2.shared.b16 {%0,%1}, [%2];"
        : "=r"(r[0]), "=r"(r[1]) : "r"(addr));
}
__device__ __forceinline__ void ldsm2t(uint32_t* r, uint32_t addr) {
    asm volatile("ldmatrix.sync.aligned.m8n8.x2.trans.shared.b16 {%0,%1}, [%2];"
        : "=r"(r[0]), "=r"(r[1]) : "r"(addr));
}

// ---------------------------------------------------------------------------
// Split-bf16 tensor-core GEMM (R12-proven exact): bf16 hi/lo smem + LDSM.
// C[M,N] = A[M,K] @ B[K,N]; CTA tile 128x128, BK=32, 256 threads (8 warps 2x4).
// Pipeline: store(cur) -> prefetch(next) -> sync -> mma(cur).
// ---------------------------------------------------------------------------
#define BM 128
#define BN 128
#define BK 32
#define A_ST   5120     // stage stride, uint16 elems (128*40)
#define B_ST   4352     // stage stride, uint16 elems (32*136)
#define OFF_AL (2*A_ST)
#define OFF_BH (4*A_ST)
#define OFF_BL (4*A_ST + 2*B_ST)
#define SMEM_GEMM ((4*A_ST + 4*B_ST) * 2)   // 75776 B
#define GTHREADS 256

__device__ __forceinline__
void gemm_body(const float* __restrict__ A, const float* __restrict__ Bg,
               float* __restrict__ C, int N, int K, int bx)
{
    extern __shared__ char smraw[];
    uint16_t* Ah = (uint16_t*)smraw;
    uint16_t* Al = Ah + OFF_AL;
    uint16_t* Bh = Ah + OFF_BH;
    uint16_t* Bl = Ah + OFF_BL;

    const int tid  = threadIdx.x;
    const int lane = tid & 31;
    const int wid  = tid >> 5;
    const int wm   = wid & 1;
    const int wn   = wid >> 1;
    const int m0   = blockIdx.y * BM;
    const int n0   = bx * BN;
    const int lg   = lane >> 2;
    const int lt   = lane & 3;

    // LDSM lane-address components (byte offsets)
    const int rowA = ((lane >> 3) & 1) * 8 + (lane & 7);
    const int colA = (lane >> 4) * 8;
    const uint32_t aLane = (uint32_t)(rowA * 40 + colA) * 2;
    const uint32_t bLane = (uint32_t)((lane & 15) * 136) * 2;

    const uint32_t ahB0 = smem_u32(Ah);
    const uint32_t alB0 = smem_u32(Al);
    const uint32_t bhB0 = smem_u32(Bh);
    const uint32_t blB0 = smem_u32(Bl);

    // per-thread fill coordinates
    int aR[4], aK[4], bR[4], bC[4];
    #pragma unroll
    for (int i = 0; i < 4; i++) {
        int idx4 = tid + i * GTHREADS;  // 0..1023
        aR[i] = idx4 >> 3;              // 0..127
        aK[i] = (idx4 & 7) * 4;         // 0..28
        bR[i] = idx4 >> 5;              // 0..31
        bC[i] = (idx4 & 31) * 4;        // 0..124
    }

    float4 pa[4], pb[4];
    #pragma unroll
    for (int i = 0; i < 4; i++) {
        pa[i] = *(const float4*)(A  + (size_t)(m0 + aR[i]) * K + aK[i]);
        pb[i] = *(const float4*)(Bg + (size_t)bR[i] * N + n0 + bC[i]);
    }

    float acc[4][4][4] = {};
    const int nk = K / BK;

    for (int c = 0; c < nk; c++) {
        const int cur = c & 1;
        // ---- convert + store current chunk ----
        #pragma unroll
        for (int i = 0; i < 4; i++) {
            uint32_t h01, l01, h23, l23;
            split_pair(pa[i].x, pa[i].y, h01, l01);
            split_pair(pa[i].z, pa[i].w, h23, l23);
            int offA = cur * A_ST + aR[i] * 40 + aK[i];
            *(uint2*)(Ah + offA) = make_uint2(h01, h23);
            *(uint2*)(Al + offA) = make_uint2(l01, l23);

            split_pair(pb[i].x, pb[i].y, h01, l01);
            split_pair(pb[i].z, pb[i].w, h23, l23);
            int offB = cur * B_ST + bR[i] * 136 + bC[i];
            *(uint2*)(Bh + offB) = make_uint2(h01, h23);
            *(uint2*)(Bl + offB) = make_uint2(l01, l23);
        }
        // ---- prefetch next chunk (LDG latency overlaps mma below) ----
        if (c + 1 < nk) {
            #pragma unroll
            for (int i = 0; i < 4; i++) {
                pa[i] = *(const float4*)(A  + (size_t)(m0 + aR[i]) * K + (c + 1) * BK + aK[i]);
                pb[i] = *(const float4*)(Bg + (size_t)((c + 1) * BK + bR[i]) * N + n0 + bC[i]);
            }
        }
        __syncthreads();

        // ---- mma from bf16 smem via LDSM ----
        const uint32_t ahB = ahB0 + cur * (A_ST * 2) + (wm * 64 * 40) * 2 + aLane;
        const uint32_t alB = alB0 + cur * (A_ST * 2) + (wm * 64 * 40) * 2 + aLane;
        const uint32_t bhB = bhB0 + cur * (B_ST * 2) + (wn * 32) * 2 + bLane;
        const uint32_t blB = blB0 + cur * (B_ST * 2) + (wn * 32) * 2 + bLane;

        #pragma unroll
        for (int ks = 0; ks < 2; ks++) {
            const int k = ks * 16;
            uint32_t ah[4][4], al[4][4];
            #pragma unroll
            for (int mi = 0; mi < 4; mi++) {
                uint32_t off = (uint32_t)(mi * 16 * 40 + k) * 2;
                ldsm4(ah[mi], ahB + off);
                ldsm4(al[mi], alB + off);
            }
            #pragma unroll
            for (int ni = 0; ni < 4; ni++) {
                uint32_t off = (uint32_t)(k * 136 + ni * 8) * 2;
                uint32_t bh[2], bl[2];
                ldsm2t(bh, bhB + off);
                ldsm2t(bl, blB + off);
                #pragma unroll
                for (int mi = 0; mi < 4; mi++) {
                    mma_bf16(acc[mi][ni], ah[mi], bh);
                    mma_bf16(acc[mi][ni], ah[mi], bl);
                    mma_bf16(acc[mi][ni], al[mi], bh);
                }
            }
        }
    }

    // ---- store C ----
    #pragma unroll
    for (int mi = 0; mi < 4; mi++) {
        #pragma unroll
        for (int ni = 0; ni < 4; ni++) {
            int row = m0 + wm * 64 + mi * 16 + lg;
            int col = n0 + wn * 32 + ni * 8 + 2 * lt;
            float2 v0 = make_float2(acc[mi][ni][0], acc[mi][ni][1]);
            float2 v1 = make_float2(acc[mi][ni][2], acc[mi][ni][3]);
            *(float2*)(C + (size_t)row * N + col)       = v0;
            *(float2*)(C + (size_t)(row + 8) * N + col) = v1;
        }
    }
}

// Fused Q/K/V projection: grid.x 0..15 -> Q, 16..19 -> K, 20..23 -> V
__global__ __launch_bounds__(GTHREADS)
void k_proj_qkv(const float* __restrict__ x, const float* __restrict__ Wq,
                const float* __restrict__ Wk, const float* __restrict__ Wv) {
    int bx = blockIdx.x;
    if (bx < 16)      gemm_body(x, Wq, g_q, EMB, EMB, bx);
    else if (bx < 20) gemm_body(x, Wk, g_k, KVD, EMB, bx - 16);
    else              gemm_body(x, Wv, g_v, KVD, EMB, bx - 20);
}
__global__ __launch_bounds__(GTHREADS)
void k_out_proj(const float* __restrict__ Wo, float* __restrict__ out) {
    gemm_body(g_attn, Wo, out, EMB, EMB, blockIdx.x);
}

// ---------------------------------------------------------------------------
// Tensor-core causal GQA flash attention v2 (R13-proven exact):
// bf16 hi/lo K/V split at fill, separate ldsm2/ldsm2t fragment loads.
// Grid (SEQ/64, NH, BSZ), 128 threads.
// ---------------------------------------------------------------------------
#define PK 72   // bf16 row pitch (144 B)

__global__ __launch_bounds__(128)
void attn_tc()
{
    __shared__ uint16_t sKh[64][PK], sKl[64][PK];
    __shared__ uint16_t sVh[64][PK], sVl[64][PK];

    const int qt = blockIdx.x, h = blockIdx.y, b = blockIdx.z;
    const int kvh = h >> 2;
    const int tid = threadIdx.x;
    const int w = tid >> 5, lane = tid & 31;
    const int lg = lane >> 2, lt = lane & 3;
    const int q0 = qt * 64;
    const int qrow = q0 + w * 16;
    const float qscale = 0.125f * 1.44269504f;

    const uint32_t kLane = (uint32_t)((lane & 7) * PK + ((lane >> 3) & 1) * 8) * 2;
    const uint32_t vLane = (uint32_t)((lane & 15) * PK) * 2;
    const uint32_t kHb = smem_u32(sKh) + kLane;
    const uint32_t kLb = smem_u32(sKl) + kLane;
    const uint32_t vHb = smem_u32(sVh) + vLane;
    const uint32_t vLb = smem_u32(sVl) + vLane;

    uint32_t qh[4][4], ql[4][4];
    {
        const float* qp = g_q + (size_t)(b * SEQ + qrow) * EMB + h * HD;
        #pragma unroll
        for (int ks = 0; ks < 4; ks++) {
            int d0 = ks * 16 + 2 * lt;
            float2 v00 = *(const float2*)(qp + (size_t)lg * EMB + d0);
            float2 v10 = *(const float2*)(qp + (size_t)(lg + 8) * EMB + d0);
            float2 v01 = *(const float2*)(qp + (size_t)lg * EMB + d0 + 8);
            float2 v11 = *(const float2*)(qp + (size_t)(lg + 8) * EMB + d0 + 8);
            split_pair(v00.x * qscale, v00.y * qscale, qh[ks][0], ql[ks][0]);
            split_pair(v10.x * qscale, v10.y * qscale, qh[ks][1], ql[ks][1]);
            split_pair(v01.x * qscale, v01.y * qscale, qh[ks][2], ql[ks][2]);
            split_pair(v11.x * qscale, v11.y * qscale, qh[ks][3], ql[ks][3]);
        }
    }

    float m_lo = -1e30f, m_hi = -1e30f;
    float l_lo = 0.f, l_hi = 0.f;
    float o[8][4] = {};

    for (int kt = 0; kt <= qt; kt++) {
        const int k0 = kt * 64;
        __syncthreads();
        #pragma unroll
        for (int i = 0; i < 8; i++) {
            int idx = tid + i * 128;
            int r = idx >> 4, c4 = (idx & 15) * 4;
            size_t base = (size_t)(b * SEQ + k0 + r) * KVD + kvh * HD + c4;
            float4 kv = *(const float4*)(g_k + base);
            float4 vv = *(const float4*)(g_v + base);
            uint32_t h01, l01, h23, l23;
            split_pair(kv.x, kv.y, h01, l01);
            split_pair(kv.z, kv.w, h23, l23);
            *(uint2*)&sKh[r][c4] = make_uint2(h01, h23);
            *(uint2*)&sKl[r][c4] = make_uint2(l01, l23);
            split_pair(vv.x, vv.y, h01, l01);
            split_pair(vv.z, vv.w, h23, l23);
            *(uint2*)&sVh[r][c4] = make_uint2(h01, h23);
            *(uint2*)&sVl[r][c4] = make_uint2(l01, l23);
        }
        __syncthreads();

        float s[8][4] = {};
        #pragma unroll
        for (int ks = 0; ks < 4; ks++) {
            #pragma unroll
            for (int nb = 0; nb < 8; nb++) {
                uint32_t off = (uint32_t)(nb * 8 * PK + ks * 16) * 2;
                uint32_t bh[2], bl[2];
                ldsm2(bh, kHb + off);
                ldsm2(bl, kLb + off);
                mma_bf16(s[nb], qh[ks], bh);
                mma_bf16(s[nb], qh[ks], bl);
                mma_bf16(s[nb], ql[ks], bh);
            }
        }

        if (kt == qt) {
            #pragma unroll
            for (int nb = 0; nb < 8; nb++) {
                int col = k0 + nb * 8 + 2 * lt;
                int rlo = qrow + lg, rhi = qrow + lg + 8;
                if (col     > rlo) s[nb][0] = -1e30f;
                if (col + 1 > rlo) s[nb][1] = -1e30f;
                if (col     > rhi) s[nb][2] = -1e30f;
                if (col + 1 > rhi) s[nb][3] = -1e30f;
            }
        }

        float tm_lo = -1e30f, tm_hi = -1e30f;
        #pragma unroll
        for (int nb = 0; nb < 8; nb++) {
            tm_lo = fmaxf(tm_lo, fmaxf(s[nb][0], s[nb][1]));
            tm_hi = fmaxf(tm_hi, fmaxf(s[nb][2], s[nb][3]));
        }
        #pragma unroll
        for (int off = 1; off <= 2; off <<= 1) {
            tm_lo = fmaxf(tm_lo, __shfl_xor_sync(0xffffffffu, tm_lo, off));
            tm_hi = fmaxf(tm_hi, __shfl_xor_sync(0xffffffffu, tm_hi, off));
        }
        float mn_lo = fmaxf(m_lo, tm_lo);
        float mn_hi = fmaxf(m_hi, tm_hi);
        float sc_lo = exp2f(m_lo - mn_lo);
        float sc_hi = exp2f(m_hi - mn_hi);
        m_lo = mn_lo; m_hi = mn_hi;

        float ps_lo = 0.f, ps_hi = 0.f;
        #pragma unroll
        for (int nb = 0; nb < 8; nb++) {
            s[nb][0] = exp2f(s[nb][0] - mn_lo);
            s[nb][1] = exp2f(s[nb][1] - mn_lo);
            s[nb][2] = exp2f(s[nb][2] - mn_hi);
            s[nb][3] = exp2f(s[nb][3] - mn_hi);
            ps_lo += s[nb][0] + s[nb][1];
            ps_hi += s[nb][2] + s[nb][3];
        }
        l_lo = l_lo * sc_lo + ps_lo;
        l_hi = l_hi * sc_hi + ps_hi;
        #pragma unroll
        for (int nbd = 0; nbd < 8; nbd++) {
            o[nbd][0] *= sc_lo; o[nbd][1] *= sc_lo;
            o[nbd][2] *= sc_hi; o[nbd][3] *= sc_hi;
        }

        #pragma unroll
        for (int kb = 0; kb < 4; kb++) {
            uint32_t ph[4], pl[4];
            split_pair(s[2*kb][0],     s[2*kb][1],     ph[0], pl[0]);
            split_pair(s[2*kb][2],     s[2*kb][3],     ph[1], pl[1]);
            split_pair(s[2*kb + 1][0], s[2*kb + 1][1], ph[2], pl[2]);
            split_pair(s[2*kb + 1][2], s[2*kb + 1][3], ph[3], pl[3]);
            #pragma unroll
            for (int nbd = 0; nbd < 8; nbd++) {
                uint32_t off = (uint32_t)(kb * 16 * PK + nbd * 8) * 2;
                uint32_t vh[2], vl[2];
                ldsm2t(vh, vHb + off);
                ldsm2t(vl, vLb + off);
                mma_bf16(o[nbd], ph, vh);
                mma_bf16(o[nbd], ph, vl);
                mma_bf16(o[nbd], pl, vh);
            }
        }
    }

    #pragma unroll
    for (int off = 1; off <= 2; off <<= 1) {
        l_lo += __shfl_xor_sync(0xffffffffu, l_lo, off);
        l_hi += __shfl_xor_sync(0xffffffffu, l_hi, off);
    }
    float inv_lo = 1.0f / l_lo, inv_hi = 1.0f / l_hi;
    float* op = g_attn + (size_t)(b * SEQ + qrow) * EMB + h * HD;
    #pragma unroll
    for (int nbd = 0; nbd < 8; nbd++) {
        int dcol = nbd * 8 + 2 * lt;
        *(float2*)(op + (size_t)lg * EMB + dcol) =
            make_float2(o[nbd][0] * inv_lo, o[nbd][1] * inv_lo);
        *(float2*)(op + (size_t)(lg + 8) * EMB + dcol) =
            make_float2(o[nbd][2] * inv_hi, o[nbd][3] * inv_hi);
    }
}

// ---------------------------------------------------------------------------
extern "C" void kernel_launch(void* const* d_in, const int* in_sizes, int n_in,
                              void* d_out, int out_size)
{
    const float* x  = (const float*)d_in[0];
    const float* Wq = (const float*)d_in[1];
    const float* Wk = (const float*)d_in[2];
    const float* Wv = (const float*)d_in[3];
    const float* Wo = (const float*)d_in[4];
    float* out = (float*)d_out;

    cudaFuncSetAttribute(k_proj_qkv, cudaFuncAttributeMaxDynamicSharedMemorySize, SMEM_GEMM);
    cudaFuncSetAttribute(k_out_proj, cudaFuncAttributeMaxDynamicSharedMemorySize, SMEM_GEMM);

    k_proj_qkv<<<dim3(24, MTOT / BM), GTHREADS, SMEM_GEMM>>>(x, Wq, Wk, Wv);
    attn_tc<<<dim3(SEQ / 64, NH, BSZ), 128>>>();
    k_out_proj<<<dim3(EMB / BN, MTOT / BM), GTHREADS, SMEM_GEMM>>>(Wo, out);
}